// round 7
// baseline (speedup 1.0000x reference)
#include <cuda_runtime.h>
#include <cuda_bf16.h>
#include <mma.h>

using namespace nvcuda;

#define NNODES 50000
#define NPAD   50176
#define EDGES  800000
#define DD 128
#define LN_EPS 1e-5f

// ---- scratch (device globals; no allocation allowed) ----
__device__ __nv_bfloat16 g_ah[(size_t)NPAD * DD];  // SpMM out, bf16 hi
__device__ __nv_bfloat16 g_al[(size_t)NPAD * DD];  // SpMM out, bf16 lo
__device__ float g_h1[(size_t)NNODES * DD];        // layer-1 output (fp32)
__device__ float g_iso[NNODES];
__device__ float g_isi[NNODES];
__device__ int   g_din[NNODES];
__device__ int   g_dout[NNODES];
__device__ int   g_cnt[NNODES];
__device__ int   g_scan[NNODES];
__device__ int   g_bsum[64];
__device__ int   g_off[NNODES + 1];
__device__ int   g_csr_src[EDGES];
__device__ __nv_bfloat16 g_w1h[DD * DD], g_w1l[DD * DD];
__device__ __nv_bfloat16 g_w2h[DD * DD], g_w2l[DD * DD];

// ---- CSR build ----
__global__ void zero_counts(int n) {
    int i = blockIdx.x * blockDim.x + threadIdx.x;
    if (i < n) { g_din[i] = 0; g_dout[i] = 0; g_cnt[i] = 0; }
}

__global__ void deg_count(const int* __restrict__ src,
                          const int* __restrict__ dst, int e) {
    int i = blockIdx.x * blockDim.x + threadIdx.x;
    if (i < e) {
        atomicAdd(&g_dout[src[i]], 1);
        atomicAdd(&g_din[dst[i]], 1);
    }
}

__global__ void scan_blocks(int n) {
    __shared__ int sh[1024];
    int gid = blockIdx.x * 1024 + threadIdx.x;
    int v = (gid < n) ? g_din[gid] : 0;
    sh[threadIdx.x] = v;
    __syncthreads();
#pragma unroll
    for (int off = 1; off < 1024; off <<= 1) {
        int t = (threadIdx.x >= off) ? sh[threadIdx.x - off] : 0;
        __syncthreads();
        sh[threadIdx.x] += t;
        __syncthreads();
    }
    if (gid < n) g_scan[gid] = sh[threadIdx.x];          // inclusive
    if (threadIdx.x == 1023) g_bsum[blockIdx.x] = sh[1023];
}

// warp-parallel exclusive scan of <=64 partials
__global__ void scan_partials(int nb) {
    int t = threadIdx.x;
    int v = (t < nb) ? g_bsum[t] : 0;
    int lane = t & 31, w = t >> 5;
    int x = v;
#pragma unroll
    for (int o = 1; o < 32; o <<= 1) {
        int y = __shfl_up_sync(0xffffffffu, x, o);
        if (lane >= o) x += y;
    }
    __shared__ int wsum[2];
    if (lane == 31) wsum[w] = x;
    __syncthreads();
    if (w == 1) x += wsum[0];
    if (t < nb) g_bsum[t] = x - v;                       // exclusive
}

__global__ void finalize_off(int n, int e) {
    int gid = blockIdx.x * blockDim.x + threadIdx.x;
    if (gid < n) {
        int incl = g_scan[gid] + g_bsum[gid >> 10];
        g_off[gid] = incl - g_din[gid];
        g_iso[gid] = rsqrtf(fmaxf((float)g_dout[gid], 1.f));
        g_isi[gid] = rsqrtf(fmaxf((float)g_din[gid], 1.f));
    }
    if (gid == 0) g_off[n] = e;
}

__global__ void fill_csr(const int* __restrict__ src,
                         const int* __restrict__ dst, int e) {
    int i = blockIdx.x * blockDim.x + threadIdx.x;
    if (i < e) {
        int d = dst[i];
        int pos = g_off[d] + atomicAdd(&g_cnt[d], 1);
        g_csr_src[pos] = src[i];
    }
}

// ---- split W1,W2 into bf16 hi/lo ----
__global__ void convert_w(const float* __restrict__ W1,
                          const float* __restrict__ W2) {
    int i = blockIdx.x * blockDim.x + threadIdx.x;
    if (i < DD * DD) {
        float w = W1[i];
        __nv_bfloat16 h = __float2bfloat16(w);
        g_w1h[i] = h;
        g_w1l[i] = __float2bfloat16(w - __bfloat162float(h));
        w = W2[i];
        h = __float2bfloat16(w);
        g_w2h[i] = h;
        g_w2l[i] = __float2bfloat16(w - __bfloat162float(h));
    }
}

// ---- pull-model SpMM: one warp per dst node; emits bf16 hi/lo split ----
__global__ void gather_spmm(const float* __restrict__ h, int n) {
    const float* hp = h ? h : g_h1;
    int w = (blockIdx.x * blockDim.x + threadIdx.x) >> 5;
    int lane = threadIdx.x & 31;
    if (w >= n) return;
    int beg = g_off[w], end = g_off[w + 1];
    float4 acc = make_float4(0.f, 0.f, 0.f, 0.f);

    int i = beg;
    for (; i + 4 <= end; i += 4) {
        int s0 = g_csr_src[i + 0];
        int s1 = g_csr_src[i + 1];
        int s2 = g_csr_src[i + 2];
        int s3 = g_csr_src[i + 3];
        float c0 = g_iso[s0], c1 = g_iso[s1], c2 = g_iso[s2], c3 = g_iso[s3];
        float4 v0 = reinterpret_cast<const float4*>(hp + (size_t)s0 * DD)[lane];
        float4 v1 = reinterpret_cast<const float4*>(hp + (size_t)s1 * DD)[lane];
        float4 v2 = reinterpret_cast<const float4*>(hp + (size_t)s2 * DD)[lane];
        float4 v3 = reinterpret_cast<const float4*>(hp + (size_t)s3 * DD)[lane];
        acc.x = fmaf(c0, v0.x, fmaf(c1, v1.x, fmaf(c2, v2.x, fmaf(c3, v3.x, acc.x))));
        acc.y = fmaf(c0, v0.y, fmaf(c1, v1.y, fmaf(c2, v2.y, fmaf(c3, v3.y, acc.y))));
        acc.z = fmaf(c0, v0.z, fmaf(c1, v1.z, fmaf(c2, v2.z, fmaf(c3, v3.z, acc.z))));
        acc.w = fmaf(c0, v0.w, fmaf(c1, v1.w, fmaf(c2, v2.w, fmaf(c3, v3.w, acc.w))));
    }
    for (; i < end; i++) {
        int s = g_csr_src[i];
        float c = g_iso[s];
        float4 v = reinterpret_cast<const float4*>(hp + (size_t)s * DD)[lane];
        acc.x = fmaf(c, v.x, acc.x);
        acc.y = fmaf(c, v.y, acc.y);
        acc.z = fmaf(c, v.z, acc.z);
        acc.w = fmaf(c, v.w, acc.w);
    }
    float si = g_isi[w];
    acc.x *= si; acc.y *= si; acc.z *= si; acc.w *= si;

    size_t base = (size_t)w * DD + lane * 4;
    __nv_bfloat16 hx = __float2bfloat16(acc.x);
    __nv_bfloat16 hy = __float2bfloat16(acc.y);
    __nv_bfloat16 hz = __float2bfloat16(acc.z);
    __nv_bfloat16 hw = __float2bfloat16(acc.w);
    *reinterpret_cast<__nv_bfloat162*>(g_ah + base)     = __nv_bfloat162(hx, hy);
    *reinterpret_cast<__nv_bfloat162*>(g_ah + base + 2) = __nv_bfloat162(hz, hw);
    __nv_bfloat16 lx = __float2bfloat16(acc.x - __bfloat162float(hx));
    __nv_bfloat16 ly = __float2bfloat16(acc.y - __bfloat162float(hy));
    __nv_bfloat16 lz = __float2bfloat16(acc.z - __bfloat162float(hz));
    __nv_bfloat16 lw = __float2bfloat16(acc.w - __bfloat162float(hw));
    *reinterpret_cast<__nv_bfloat162*>(g_al + base)     = __nv_bfloat162(lx, ly);
    *reinterpret_cast<__nv_bfloat162*>(g_al + base + 2) = __nv_bfloat162(lz, lw);
}

// ---- tensor-core GEMM (bf16 split, fp32 acc) + bias + LayerNorm + ReLU ----
// tile: 64 rows x 128 cols, full K=128. 256 threads = 8 warps (4M x 2N).
// dynamic smem: Bh(32K) Bl(32K) Ah(16K) Al(16K) = 96KB; Cf overlaps Ah/Al.
__global__ __launch_bounds__(256)
void gemm_wmma_ln(int layer, const float* __restrict__ b,
                  const float* __restrict__ gamma,
                  const float* __restrict__ beta,
                  float* __restrict__ outparam, int n) {
    extern __shared__ char sm[];
    __nv_bfloat16* Bh = (__nv_bfloat16*)sm;                  // 128x128
    __nv_bfloat16* Bl = Bh + DD * DD;
    __nv_bfloat16* Ah = Bl + DD * DD;                        // 64x128
    __nv_bfloat16* Al = Ah + 64 * DD;
    float* Cf = (float*)(sm + 64 * 1024);                    // 64x128 fp32 (over Ah/Al)
    __shared__ float muArr[64], invArr[64];

    const __nv_bfloat16* Wh = (layer == 1) ? g_w1h : g_w2h;
    const __nv_bfloat16* Wl = (layer == 1) ? g_w1l : g_w2l;
    float* op = (layer == 1) ? g_h1 : outparam;

    int tid = threadIdx.x;
    int rowBase = blockIdx.x * 64;

    // stage B (weights) hi+lo: 2048 uint4 each
    {
        const uint4* sBh = (const uint4*)Wh;
        const uint4* sBl = (const uint4*)Wl;
        uint4* dBh = (uint4*)Bh;
        uint4* dBl = (uint4*)Bl;
#pragma unroll
        for (int i = 0; i < 8; i++) {
            dBh[tid + i * 256] = sBh[tid + i * 256];
            dBl[tid + i * 256] = sBl[tid + i * 256];
        }
        // stage A hi+lo: 1024 uint4 each (rows may extend into zero padding)
        const uint4* sAh = (const uint4*)(g_ah + (size_t)rowBase * DD);
        const uint4* sAl = (const uint4*)(g_al + (size_t)rowBase * DD);
        uint4* dAh = (uint4*)Ah;
        uint4* dAl = (uint4*)Al;
#pragma unroll
        for (int i = 0; i < 4; i++) {
            dAh[tid + i * 256] = sAh[tid + i * 256];
            dAl[tid + i * 256] = sAl[tid + i * 256];
        }
    }
    __syncthreads();

    int warp = tid >> 5;
    int wm = warp >> 1;   // 0..3
    int wn = warp & 1;    // 0..1

    wmma::fragment<wmma::accumulator, 16, 16, 16, float> acc[4];
#pragma unroll
    for (int f = 0; f < 4; f++) wmma::fill_fragment(acc[f], 0.f);

#pragma unroll
    for (int k = 0; k < 8; k++) {
        wmma::fragment<wmma::matrix_a, 16, 16, 16, __nv_bfloat16, wmma::row_major> ah, al;
        wmma::load_matrix_sync(ah, Ah + (wm * 16) * DD + k * 16, DD);
        wmma::load_matrix_sync(al, Al + (wm * 16) * DD + k * 16, DD);
#pragma unroll
        for (int nf = 0; nf < 4; nf++) {
            int col = wn * 64 + nf * 16;
            wmma::fragment<wmma::matrix_b, 16, 16, 16, __nv_bfloat16, wmma::row_major> bh, bl;
            wmma::load_matrix_sync(bh, Bh + (k * 16) * DD + col, DD);
            wmma::load_matrix_sync(bl, Bl + (k * 16) * DD + col, DD);
            wmma::mma_sync(acc[nf], ah, bh, acc[nf]);
            wmma::mma_sync(acc[nf], ah, bl, acc[nf]);
            wmma::mma_sync(acc[nf], al, bh, acc[nf]);
        }
    }
    __syncthreads();   // done reading Ah/Al before overwriting as Cf
#pragma unroll
    for (int nf = 0; nf < 4; nf++)
        wmma::store_matrix_sync(Cf + (wm * 16) * DD + wn * 64 + nf * 16,
                                acc[nf], DD, wmma::mem_row_major);
    __syncthreads();

    // ---- LN pass 1: row stats (rotated float4 reads: conflict-free) ----
    int r = tid >> 2;   // 0..63 (row)
    int q = tid & 3;    // 0..3  (32-col chunk)
    const float4* Cf4 = (const float4*)Cf;
    float s = 0.f, s2 = 0.f;
#pragma unroll
    for (int j8 = 0; j8 < 8; j8++) {
        int idx8 = (j8 + (tid & 7)) & 7;
        float4 x = Cf4[r * 32 + q * 8 + idx8];
        int col = q * 32 + idx8 * 4;
        float v0 = x.x + b[col + 0];
        float v1 = x.y + b[col + 1];
        float v2 = x.z + b[col + 2];
        float v3 = x.w + b[col + 3];
        s  += v0 + v1 + v2 + v3;
        s2 += v0 * v0 + v1 * v1 + v2 * v2 + v3 * v3;
    }
    s  += __shfl_xor_sync(0xffffffffu, s, 1);
    s2 += __shfl_xor_sync(0xffffffffu, s2, 1);
    s  += __shfl_xor_sync(0xffffffffu, s, 2);
    s2 += __shfl_xor_sync(0xffffffffu, s2, 2);
    if (q == 0) {
        float mu  = s * (1.f / 128.f);
        float var = s2 * (1.f / 128.f) - mu * mu;
        muArr[r]  = mu;
        invArr[r] = rsqrtf(var + LN_EPS);
    }
    __syncthreads();

    // ---- LN pass 2: coalesced normalize + ReLU + store ----
#pragma unroll
    for (int k = 0; k < 8; k++) {
        int idx = tid + k * 256;        // float4 index, 0..2047
        int row = idx >> 5;
        int grow = rowBase + row;
        if (grow >= n) continue;
        float4 x = Cf4[idx];
        int col = (idx & 31) * 4;
        float mu = muArr[row], inv = invArr[row];
        float y0 = (x.x + b[col + 0] - mu) * inv * gamma[col + 0] + beta[col + 0];
        float y1 = (x.y + b[col + 1] - mu) * inv * gamma[col + 1] + beta[col + 1];
        float y2 = (x.z + b[col + 2] - mu) * inv * gamma[col + 2] + beta[col + 2];
        float y3 = (x.w + b[col + 3] - mu) * inv * gamma[col + 3] + beta[col + 3];
        float4 o;
        o.x = fmaxf(y0, 0.f); o.y = fmaxf(y1, 0.f);
        o.z = fmaxf(y2, 0.f); o.w = fmaxf(y3, 0.f);
        *reinterpret_cast<float4*>(op + (size_t)grow * DD + col) = o;
    }
}

extern "C" void kernel_launch(void* const* d_in, const int* in_sizes, int n_in,
                              void* d_out, int out_size) {
    const float* features = (const float*)d_in[0];
    const int*   src      = (const int*)d_in[1];
    const int*   dst      = (const int*)d_in[2];
    const float* W1  = (const float*)d_in[3];
    const float* b1  = (const float*)d_in[4];
    const float* g1  = (const float*)d_in[5];
    const float* be1 = (const float*)d_in[6];
    const float* W2  = (const float*)d_in[7];
    const float* b2  = (const float*)d_in[8];
    const float* g2  = (const float*)d_in[9];
    const float* be2 = (const float*)d_in[10];
    float* out = (float*)d_out;

    int n = in_sizes[0] / DD;   // 50000
    int e = in_sizes[1];        // 800000

    int nBlocks    = (n + 255) / 256;
    int eBlocks    = (e + 255) / 256;
    int scanBlocks = (n + 1023) / 1024;
    int gathBlocks = (int)(((long long)n * 32 + 255) / 256);
    int gemmBlocks = (n + 63) / 64;
    const int GEMM_SMEM = 96 * 1024;

    static bool attr_set = false;
    if (!attr_set) {
        cudaFuncSetAttribute(gemm_wmma_ln,
                             cudaFuncAttributeMaxDynamicSharedMemorySize, GEMM_SMEM);
        attr_set = true;
    }

    // ---- CSR build (once, reused by both layers) ----
    zero_counts<<<nBlocks, 256>>>(n);
    deg_count<<<eBlocks, 256>>>(src, dst, e);
    scan_blocks<<<scanBlocks, 1024>>>(n);
    scan_partials<<<1, 64>>>(scanBlocks);
    finalize_off<<<nBlocks, 256>>>(n, e);
    fill_csr<<<eBlocks, 256>>>(src, dst, e);
    convert_w<<<(DD * DD + 255) / 256, 256>>>(W1, W2);

    // ---- layer 1 ----
    gather_spmm<<<gathBlocks, 256>>>(features, n);
    gemm_wmma_ln<<<gemmBlocks, 256, GEMM_SMEM>>>(1, b1, g1, be1, nullptr, n);

    // ---- layer 2 ----
    gather_spmm<<<gathBlocks, 256>>>(nullptr, n);
    gemm_wmma_ln<<<gemmBlocks, 256, GEMM_SMEM>>>(2, b2, g2, be2, out, n);
}

// round 9
// speedup vs baseline: 1.2672x; 1.2672x over previous
#include <cuda_runtime.h>
#include <cstdint>

#define NNODES 50000
#define EDGES  800000
#define DD 128
#define LN_EPS 1e-5f

// ---- scratch (device globals; no allocation allowed) ----
__device__ float g_agg[(size_t)NNODES * DD];   // SpMM output
__device__ float g_h1[(size_t)NNODES * DD];    // layer-1 output
__device__ float g_iso[NNODES];
__device__ float g_isi[NNODES];
__device__ int   g_din[NNODES];
__device__ int   g_dout[NNODES];
__device__ int   g_cnt[NNODES];
__device__ int   g_scan[NNODES];
__device__ int   g_bsum[64];
__device__ int   g_off[NNODES + 1];
__device__ int   g_csr_src[EDGES];

// ---- CSR build ----
__global__ void zero_counts(int n) {
    int i = blockIdx.x * blockDim.x + threadIdx.x;
    if (i < n) { g_din[i] = 0; g_dout[i] = 0; g_cnt[i] = 0; }
}

__global__ void deg_count(const int* __restrict__ src,
                          const int* __restrict__ dst, int e) {
    int i = blockIdx.x * blockDim.x + threadIdx.x;
    if (i < e) {
        atomicAdd(&g_dout[src[i]], 1);
        atomicAdd(&g_din[dst[i]], 1);
    }
}

__global__ void scan_blocks(int n) {
    __shared__ int sh[1024];
    int gid = blockIdx.x * 1024 + threadIdx.x;
    int v = (gid < n) ? g_din[gid] : 0;
    sh[threadIdx.x] = v;
    __syncthreads();
#pragma unroll
    for (int off = 1; off < 1024; off <<= 1) {
        int t = (threadIdx.x >= off) ? sh[threadIdx.x - off] : 0;
        __syncthreads();
        sh[threadIdx.x] += t;
        __syncthreads();
    }
    if (gid < n) g_scan[gid] = sh[threadIdx.x];          // inclusive
    if (threadIdx.x == 1023) g_bsum[blockIdx.x] = sh[1023];
}

__global__ void scan_partials(int nb) {
    int t = threadIdx.x;
    int v = (t < nb) ? g_bsum[t] : 0;
    int lane = t & 31, w = t >> 5;
    int x = v;
#pragma unroll
    for (int o = 1; o < 32; o <<= 1) {
        int y = __shfl_up_sync(0xffffffffu, x, o);
        if (lane >= o) x += y;
    }
    __shared__ int wsum[2];
    if (lane == 31) wsum[w] = x;
    __syncthreads();
    if (w == 1) x += wsum[0];
    if (t < nb) g_bsum[t] = x - v;                       // exclusive
}

__global__ void finalize_off(int n, int e) {
    int gid = blockIdx.x * blockDim.x + threadIdx.x;
    if (gid < n) {
        int incl = g_scan[gid] + g_bsum[gid >> 10];
        g_off[gid] = incl - g_din[gid];
        g_iso[gid] = rsqrtf(fmaxf((float)g_dout[gid], 1.f));
        g_isi[gid] = rsqrtf(fmaxf((float)g_din[gid], 1.f));
    }
    if (gid == 0) g_off[n] = e;
}

__global__ void fill_csr(const int* __restrict__ src,
                         const int* __restrict__ dst, int e) {
    int i = blockIdx.x * blockDim.x + threadIdx.x;
    if (i < e) {
        int d = dst[i];
        int pos = g_off[d] + atomicAdd(&g_cnt[d], 1);
        g_csr_src[pos] = src[i];
    }
}

// ---- pull-model SpMM: one warp per dst node, register accumulation ----
__global__ void gather_spmm(const float* __restrict__ h, int n) {
    const float* hp = h ? h : g_h1;
    int w = (blockIdx.x * blockDim.x + threadIdx.x) >> 5;
    int lane = threadIdx.x & 31;
    if (w >= n) return;
    int beg = g_off[w], end = g_off[w + 1];
    float4 acc = make_float4(0.f, 0.f, 0.f, 0.f);

    int i = beg;
    for (; i + 4 <= end; i += 4) {
        int s0 = g_csr_src[i + 0];
        int s1 = g_csr_src[i + 1];
        int s2 = g_csr_src[i + 2];
        int s3 = g_csr_src[i + 3];
        float c0 = g_iso[s0], c1 = g_iso[s1], c2 = g_iso[s2], c3 = g_iso[s3];
        float4 v0 = reinterpret_cast<const float4*>(hp + (size_t)s0 * DD)[lane];
        float4 v1 = reinterpret_cast<const float4*>(hp + (size_t)s1 * DD)[lane];
        float4 v2 = reinterpret_cast<const float4*>(hp + (size_t)s2 * DD)[lane];
        float4 v3 = reinterpret_cast<const float4*>(hp + (size_t)s3 * DD)[lane];
        acc.x = fmaf(c0, v0.x, fmaf(c1, v1.x, fmaf(c2, v2.x, fmaf(c3, v3.x, acc.x))));
        acc.y = fmaf(c0, v0.y, fmaf(c1, v1.y, fmaf(c2, v2.y, fmaf(c3, v3.y, acc.y))));
        acc.z = fmaf(c0, v0.z, fmaf(c1, v1.z, fmaf(c2, v2.z, fmaf(c3, v3.z, acc.z))));
        acc.w = fmaf(c0, v0.w, fmaf(c1, v1.w, fmaf(c3, v3.w, fmaf(c2, v2.w, acc.w))));
    }
    for (; i < end; i++) {
        int s = g_csr_src[i];
        float c = g_iso[s];
        float4 v = reinterpret_cast<const float4*>(hp + (size_t)s * DD)[lane];
        acc.x = fmaf(c, v.x, acc.x);
        acc.y = fmaf(c, v.y, acc.y);
        acc.z = fmaf(c, v.z, acc.z);
        acc.w = fmaf(c, v.w, acc.w);
    }
    float si = g_isi[w];
    acc.x *= si; acc.y *= si; acc.z *= si; acc.w *= si;
    reinterpret_cast<float4*>(g_agg + (size_t)w * DD)[lane] = acc;
}

// ---- packed f32x2 helpers ----
__device__ __forceinline__ unsigned long long pack2(float lo, float hi) {
    unsigned long long r;
    asm("mov.b64 %0, {%1, %2};" : "=l"(r) : "f"(lo), "f"(hi));
    return r;
}
__device__ __forceinline__ void unpack2(unsigned long long v, float& lo, float& hi) {
    asm("mov.b64 {%0, %1}, %2;" : "=f"(lo), "=f"(hi) : "l"(v));
}
__device__ __forceinline__ void fma2(unsigned long long& d, unsigned long long a,
                                     unsigned long long b) {
    asm("fma.rn.f32x2 %0, %1, %2, %3;" : "=l"(d) : "l"(a), "l"(b), "l"(d));
}

// ---- fused agg @ W + b -> LayerNorm -> ReLU, packed f32x2 math ----
// Block: 256 threads (16x16), tile 64 rows x 128 cols, BK=16.
// Thread (tx,ty): rows ty*4..+3, cols tx*8..+7 (4 packed accs per row).
// out==nullptr means write to g_h1.
__global__ __launch_bounds__(256)
void gemm_ln_relu(const float* __restrict__ W,
                  const float* __restrict__ b,
                  const float* __restrict__ gamma,
                  const float* __restrict__ beta,
                  float* __restrict__ out, int n) {
    float* op = out ? out : g_h1;

    __shared__ float As[16][68];   // [k][row], padded
    __shared__ float Bs[16][128];  // [k][col]

    int tid = threadIdx.x;
    int tx = tid & 15;   // col group (8 contiguous cols)
    int ty = tid >> 4;   // row group (4 rows)
    int rowBase = blockIdx.x * 64;

    unsigned long long acc2[4][4];
#pragma unroll
    for (int i = 0; i < 4; i++)
#pragma unroll
        for (int j = 0; j < 4; j++) acc2[i][j] = 0ull;

    int r = tid >> 2;      // 0..63
    int q = tid & 3;       // 0..3
    int grow_ld = rowBase + r;

    for (int k0 = 0; k0 < 128; k0 += 16) {
        // A tile: 64 rows x 16 k
        float4 av = make_float4(0.f, 0.f, 0.f, 0.f);
        if (grow_ld < n)
            av = *reinterpret_cast<const float4*>(
                g_agg + (size_t)grow_ld * DD + k0 + q * 4);
        As[q * 4 + 0][r] = av.x;
        As[q * 4 + 1][r] = av.y;
        As[q * 4 + 2][r] = av.z;
        As[q * 4 + 3][r] = av.w;

        // B tile: 16 k x 128 cols
#pragma unroll
        for (int u = 0; u < 2; u++) {
            int idx = tid + u * 256;
            int br = idx >> 5;
            int c4 = idx & 31;
            float4 bv = *reinterpret_cast<const float4*>(
                W + (size_t)(k0 + br) * DD + c4 * 4);
            *reinterpret_cast<float4*>(&Bs[br][c4 * 4]) = bv;
        }
        __syncthreads();

#pragma unroll
        for (int kk = 0; kk < 16; kk++) {
            float4 a4 = *reinterpret_cast<const float4*>(&As[kk][ty * 4]);
            unsigned long long a0 = pack2(a4.x, a4.x);
            unsigned long long a1 = pack2(a4.y, a4.y);
            unsigned long long a2 = pack2(a4.z, a4.z);
            unsigned long long a3 = pack2(a4.w, a4.w);
            float4 bA = *reinterpret_cast<const float4*>(&Bs[kk][tx * 8]);
            float4 bB = *reinterpret_cast<const float4*>(&Bs[kk][tx * 8 + 4]);
            unsigned long long b0 = pack2(bA.x, bA.y);
            unsigned long long b1 = pack2(bA.z, bA.w);
            unsigned long long b2 = pack2(bB.x, bB.y);
            unsigned long long b3 = pack2(bB.z, bB.w);
            fma2(acc2[0][0], a0, b0); fma2(acc2[0][1], a0, b1);
            fma2(acc2[0][2], a0, b2); fma2(acc2[0][3], a0, b3);
            fma2(acc2[1][0], a1, b0); fma2(acc2[1][1], a1, b1);
            fma2(acc2[1][2], a1, b2); fma2(acc2[1][3], a1, b3);
            fma2(acc2[2][0], a2, b0); fma2(acc2[2][1], a2, b1);
            fma2(acc2[2][2], a2, b2); fma2(acc2[2][3], a2, b3);
            fma2(acc2[3][0], a3, b0); fma2(acc2[3][1], a3, b1);
            fma2(acc2[3][2], a3, b2); fma2(acc2[3][3], a3, b3);
        }
        __syncthreads();
    }

    int colBase = tx * 8;
    float bb[8], gg[8], be8[8];
#pragma unroll
    for (int j = 0; j < 8; j++) {
        bb[j]  = b[colBase + j];
        gg[j]  = gamma[colBase + j];
        be8[j] = beta[colBase + j];
    }

    // epilogue: +bias, LayerNorm over the 128-wide row, ReLU
#pragma unroll
    for (int i = 0; i < 4; i++) {
        int grow = rowBase + ty * 4 + i;
        float v[8];
#pragma unroll
        for (int j = 0; j < 4; j++)
            unpack2(acc2[i][j], v[2 * j], v[2 * j + 1]);
        float s = 0.f, s2 = 0.f;
#pragma unroll
        for (int j = 0; j < 8; j++) {
            v[j] += bb[j];
            s += v[j];
            s2 += v[j] * v[j];
        }
        // reduce across the 16 lanes (tx) that share this row
#pragma unroll
        for (int m = 1; m < 16; m <<= 1) {
            s  += __shfl_xor_sync(0xffffffffu, s,  m);
            s2 += __shfl_xor_sync(0xffffffffu, s2, m);
        }
        float mu  = s * (1.f / 128.f);
        float var = s2 * (1.f / 128.f) - mu * mu;
        float inv = rsqrtf(var + LN_EPS);
        if (grow < n) {
            float4 o0, o1;
            o0.x = fmaxf((v[0] - mu) * inv * gg[0] + be8[0], 0.f);
            o0.y = fmaxf((v[1] - mu) * inv * gg[1] + be8[1], 0.f);
            o0.z = fmaxf((v[2] - mu) * inv * gg[2] + be8[2], 0.f);
            o0.w = fmaxf((v[3] - mu) * inv * gg[3] + be8[3], 0.f);
            o1.x = fmaxf((v[4] - mu) * inv * gg[4] + be8[4], 0.f);
            o1.y = fmaxf((v[5] - mu) * inv * gg[5] + be8[5], 0.f);
            o1.z = fmaxf((v[6] - mu) * inv * gg[6] + be8[6], 0.f);
            o1.w = fmaxf((v[7] - mu) * inv * gg[7] + be8[7], 0.f);
            float* orow = op + (size_t)grow * DD + colBase;
            *reinterpret_cast<float4*>(orow)     = o0;
            *reinterpret_cast<float4*>(orow + 4) = o1;
        }
    }
}

extern "C" void kernel_launch(void* const* d_in, const int* in_sizes, int n_in,
                              void* d_out, int out_size) {
    const float* features = (const float*)d_in[0];
    const int*   src      = (const int*)d_in[1];
    const int*   dst      = (const int*)d_in[2];
    const float* W1  = (const float*)d_in[3];
    const float* b1  = (const float*)d_in[4];
    const float* g1  = (const float*)d_in[5];
    const float* be1 = (const float*)d_in[6];
    const float* W2  = (const float*)d_in[7];
    const float* b2  = (const float*)d_in[8];
    const float* g2  = (const float*)d_in[9];
    const float* be2 = (const float*)d_in[10];
    float* out = (float*)d_out;

    int n = in_sizes[0] / DD;   // 50000
    int e = in_sizes[1];        // 800000

    int nBlocks    = (n + 255) / 256;
    int eBlocks    = (e + 255) / 256;
    int scanBlocks = (n + 1023) / 1024;
    int gathBlocks = (int)(((long long)n * 32 + 255) / 256);
    int gemmBlocks = (n + 63) / 64;

    // ---- CSR build (once, reused by both layers) ----
    zero_counts<<<nBlocks, 256>>>(n);
    deg_count<<<eBlocks, 256>>>(src, dst, e);
    scan_blocks<<<scanBlocks, 1024>>>(n);
    scan_partials<<<1, 64>>>(scanBlocks);
    finalize_off<<<nBlocks, 256>>>(n, e);
    fill_csr<<<eBlocks, 256>>>(src, dst, e);

    // ---- layer 1 ----
    gather_spmm<<<gathBlocks, 256>>>(features, n);
    gemm_ln_relu<<<gemmBlocks, 256>>>(W1, b1, g1, be1, nullptr, n);

    // ---- layer 2 ----
    gather_spmm<<<gathBlocks, 256>>>(nullptr, n);
    gemm_ln_relu<<<gemmBlocks, 256>>>(W2, b2, g2, be2, out, n);
}

// round 10
// speedup vs baseline: 1.4068x; 1.1102x over previous
#include <cuda_runtime.h>
#include <cstdint>

#define NNODES 50000
#define EDGES  800000
#define DD 128
#define LN_EPS 1e-5f

// ---- scratch (device globals; no allocation allowed) ----
__device__ float g_agg[(size_t)NNODES * DD];   // SpMM output
__device__ float g_h1[(size_t)NNODES * DD];    // layer-1 output
__device__ float g_iso[NNODES];
__device__ float g_isi[NNODES];
__device__ int   g_din[NNODES];
__device__ int   g_dout[NNODES];
__device__ int   g_cnt[NNODES];
__device__ int   g_scan[NNODES];
__device__ int   g_bsum[64];
__device__ int   g_off[NNODES + 1];
__device__ int   g_csr_src[EDGES];

// ---- CSR build ----
__global__ void zero_counts(int n) {
    int i = blockIdx.x * blockDim.x + threadIdx.x;
    if (i < n) { g_din[i] = 0; g_dout[i] = 0; g_cnt[i] = 0; }
}

__global__ void deg_count(const int* __restrict__ src,
                          const int* __restrict__ dst, int e) {
    int i = blockIdx.x * blockDim.x + threadIdx.x;
    if (i < e) {
        atomicAdd(&g_dout[src[i]], 1);
        atomicAdd(&g_din[dst[i]], 1);
    }
}

__global__ void scan_blocks(int n) {
    __shared__ int sh[1024];
    int gid = blockIdx.x * 1024 + threadIdx.x;
    int v = (gid < n) ? g_din[gid] : 0;
    sh[threadIdx.x] = v;
    __syncthreads();
#pragma unroll
    for (int off = 1; off < 1024; off <<= 1) {
        int t = (threadIdx.x >= off) ? sh[threadIdx.x - off] : 0;
        __syncthreads();
        sh[threadIdx.x] += t;
        __syncthreads();
    }
    if (gid < n) g_scan[gid] = sh[threadIdx.x];          // inclusive
    if (threadIdx.x == 1023) g_bsum[blockIdx.x] = sh[1023];
}

__global__ void scan_partials(int nb) {
    int t = threadIdx.x;
    int v = (t < nb) ? g_bsum[t] : 0;
    int lane = t & 31, w = t >> 5;
    int x = v;
#pragma unroll
    for (int o = 1; o < 32; o <<= 1) {
        int y = __shfl_up_sync(0xffffffffu, x, o);
        if (lane >= o) x += y;
    }
    __shared__ int wsum[2];
    if (lane == 31) wsum[w] = x;
    __syncthreads();
    if (w == 1) x += wsum[0];
    if (t < nb) g_bsum[t] = x - v;                       // exclusive
}

__global__ void finalize_off(int n, int e) {
    int gid = blockIdx.x * blockDim.x + threadIdx.x;
    if (gid < n) {
        int incl = g_scan[gid] + g_bsum[gid >> 10];
        g_off[gid] = incl - g_din[gid];
        g_iso[gid] = rsqrtf(fmaxf((float)g_dout[gid], 1.f));
        g_isi[gid] = rsqrtf(fmaxf((float)g_din[gid], 1.f));
    }
    if (gid == 0) g_off[n] = e;
}

__global__ void fill_csr(const int* __restrict__ src,
                         const int* __restrict__ dst, int e) {
    int i = blockIdx.x * blockDim.x + threadIdx.x;
    if (i < e) {
        int d = dst[i];
        int pos = g_off[d] + atomicAdd(&g_cnt[d], 1);
        g_csr_src[pos] = src[i];
    }
}

// ---- pull-model SpMM: one warp per dst node, register accumulation ----
__global__ void gather_spmm(const float* __restrict__ h, int n) {
    const float* hp = h ? h : g_h1;
    int w = (blockIdx.x * blockDim.x + threadIdx.x) >> 5;
    int lane = threadIdx.x & 31;
    if (w >= n) return;
    int beg = g_off[w], end = g_off[w + 1];
    float4 acc = make_float4(0.f, 0.f, 0.f, 0.f);

    int i = beg;
    for (; i + 4 <= end; i += 4) {
        int s0 = g_csr_src[i + 0];
        int s1 = g_csr_src[i + 1];
        int s2 = g_csr_src[i + 2];
        int s3 = g_csr_src[i + 3];
        float c0 = g_iso[s0], c1 = g_iso[s1], c2 = g_iso[s2], c3 = g_iso[s3];
        float4 v0 = reinterpret_cast<const float4*>(hp + (size_t)s0 * DD)[lane];
        float4 v1 = reinterpret_cast<const float4*>(hp + (size_t)s1 * DD)[lane];
        float4 v2 = reinterpret_cast<const float4*>(hp + (size_t)s2 * DD)[lane];
        float4 v3 = reinterpret_cast<const float4*>(hp + (size_t)s3 * DD)[lane];
        acc.x = fmaf(c0, v0.x, fmaf(c1, v1.x, fmaf(c2, v2.x, fmaf(c3, v3.x, acc.x))));
        acc.y = fmaf(c0, v0.y, fmaf(c1, v1.y, fmaf(c2, v2.y, fmaf(c3, v3.y, acc.y))));
        acc.z = fmaf(c0, v0.z, fmaf(c1, v1.z, fmaf(c2, v2.z, fmaf(c3, v3.z, acc.z))));
        acc.w = fmaf(c0, v0.w, fmaf(c1, v1.w, fmaf(c2, v2.w, fmaf(c3, v3.w, acc.w))));
    }
    for (; i < end; i++) {
        int s = g_csr_src[i];
        float c = g_iso[s];
        float4 v = reinterpret_cast<const float4*>(hp + (size_t)s * DD)[lane];
        acc.x = fmaf(c, v.x, acc.x);
        acc.y = fmaf(c, v.y, acc.y);
        acc.z = fmaf(c, v.z, acc.z);
        acc.w = fmaf(c, v.w, acc.w);
    }
    float si = g_isi[w];
    acc.x *= si; acc.y *= si; acc.z *= si; acc.w *= si;
    reinterpret_cast<float4*>(g_agg + (size_t)w * DD)[lane] = acc;
}

// ---- packed f32x2 helpers ----
__device__ __forceinline__ void unpack2(unsigned long long v, float& lo, float& hi) {
    asm("mov.b64 {%0, %1}, %2;" : "=f"(lo), "=f"(hi) : "l"(v));
}
__device__ __forceinline__ void fma2(unsigned long long& d, unsigned long long a,
                                     unsigned long long b) {
    asm("fma.rn.f32x2 %0, %1, %2, %3;" : "=l"(d) : "l"(a), "l"(b), "l"(d));
}

// ---- fused agg @ W + b -> LayerNorm -> ReLU, pack-free f32x2 math ----
// Block: 256 threads (16x16), tile 64 rows x 128 cols, BK=16.
// Thread (tx,ty): rows ty*4..+3, col pairs {2tx+32p, 2tx+1+32p}, p=0..3.
// A stored DUPLICATED in smem so LDS.64 yields {a,a}; B pairs are contiguous.
// out==nullptr means write to g_h1.
__global__ __launch_bounds__(256)
void gemm_ln_relu(const float* __restrict__ W,
                  const float* __restrict__ b,
                  const float* __restrict__ gamma,
                  const float* __restrict__ beta,
                  float* __restrict__ out, int n) {
    float* op = out ? out : g_h1;

    __shared__ float As2[16][128];  // [k][2*row] duplicated pairs
    __shared__ float Bs[16][128];   // [k][col]

    int tid = threadIdx.x;
    int tx = tid & 15;   // col-pair group
    int ty = tid >> 4;   // row group (4 rows)
    int rowBase = blockIdx.x * 64;

    unsigned long long acc2[4][4];
#pragma unroll
    for (int i = 0; i < 4; i++)
#pragma unroll
        for (int j = 0; j < 4; j++) acc2[i][j] = 0ull;

    int r = tid >> 2;      // 0..63
    int q = tid & 3;       // 0..3
    int grow_ld = rowBase + r;

    for (int k0 = 0; k0 < 128; k0 += 16) {
        // A tile, duplicated: As2[k][2r] = As2[k][2r+1] = A[r][k]
        float4 av = make_float4(0.f, 0.f, 0.f, 0.f);
        if (grow_ld < n)
            av = *reinterpret_cast<const float4*>(
                g_agg + (size_t)grow_ld * DD + k0 + q * 4);
        *reinterpret_cast<float2*>(&As2[q * 4 + 0][2 * r]) = make_float2(av.x, av.x);
        *reinterpret_cast<float2*>(&As2[q * 4 + 1][2 * r]) = make_float2(av.y, av.y);
        *reinterpret_cast<float2*>(&As2[q * 4 + 2][2 * r]) = make_float2(av.z, av.z);
        *reinterpret_cast<float2*>(&As2[q * 4 + 3][2 * r]) = make_float2(av.w, av.w);

        // B tile: 16 k x 128 cols
#pragma unroll
        for (int u = 0; u < 2; u++) {
            int idx = tid + u * 256;
            int br = idx >> 5;
            int c4 = idx & 31;
            float4 bv = *reinterpret_cast<const float4*>(
                W + (size_t)(k0 + br) * DD + c4 * 4);
            *reinterpret_cast<float4*>(&Bs[br][c4 * 4]) = bv;
        }
        __syncthreads();

#pragma unroll
        for (int kk = 0; kk < 16; kk++) {
            unsigned long long a0 = *reinterpret_cast<const unsigned long long*>(
                &As2[kk][2 * (ty * 4 + 0)]);
            unsigned long long a1 = *reinterpret_cast<const unsigned long long*>(
                &As2[kk][2 * (ty * 4 + 1)]);
            unsigned long long a2 = *reinterpret_cast<const unsigned long long*>(
                &As2[kk][2 * (ty * 4 + 2)]);
            unsigned long long a3 = *reinterpret_cast<const unsigned long long*>(
                &As2[kk][2 * (ty * 4 + 3)]);
            unsigned long long b0 = *reinterpret_cast<const unsigned long long*>(
                &Bs[kk][2 * tx]);
            unsigned long long b1 = *reinterpret_cast<const unsigned long long*>(
                &Bs[kk][2 * tx + 32]);
            unsigned long long b2 = *reinterpret_cast<const unsigned long long*>(
                &Bs[kk][2 * tx + 64]);
            unsigned long long b3 = *reinterpret_cast<const unsigned long long*>(
                &Bs[kk][2 * tx + 96]);
            fma2(acc2[0][0], a0, b0); fma2(acc2[0][1], a0, b1);
            fma2(acc2[0][2], a0, b2); fma2(acc2[0][3], a0, b3);
            fma2(acc2[1][0], a1, b0); fma2(acc2[1][1], a1, b1);
            fma2(acc2[1][2], a1, b2); fma2(acc2[1][3], a1, b3);
            fma2(acc2[2][0], a2, b0); fma2(acc2[2][1], a2, b1);
            fma2(acc2[2][2], a2, b2); fma2(acc2[2][3], a2, b3);
            fma2(acc2[3][0], a3, b0); fma2(acc2[3][1], a3, b1);
            fma2(acc2[3][2], a3, b2); fma2(acc2[3][3], a3, b3);
        }
        __syncthreads();
    }

    // per-thread column constants: cols 2tx+32p, 2tx+1+32p
    float bb[8], gg[8], be8[8];
#pragma unroll
    for (int p = 0; p < 4; p++) {
        int col = 2 * tx + 32 * p;
        bb[2 * p]      = b[col];
        bb[2 * p + 1]  = b[col + 1];
        gg[2 * p]      = gamma[col];
        gg[2 * p + 1]  = gamma[col + 1];
        be8[2 * p]     = beta[col];
        be8[2 * p + 1] = beta[col + 1];
    }

    // epilogue: +bias, LayerNorm over the 128-wide row, ReLU
#pragma unroll
    for (int i = 0; i < 4; i++) {
        int grow = rowBase + ty * 4 + i;
        float v[8];
#pragma unroll
        for (int p = 0; p < 4; p++)
            unpack2(acc2[i][p], v[2 * p], v[2 * p + 1]);
        float s = 0.f, s2 = 0.f;
#pragma unroll
        for (int j = 0; j < 8; j++) {
            v[j] += bb[j];
            s += v[j];
            s2 += v[j] * v[j];
        }
        // reduce across the 16 lanes (tx) that share this row
#pragma unroll
        for (int m = 1; m < 16; m <<= 1) {
            s  += __shfl_xor_sync(0xffffffffu, s,  m);
            s2 += __shfl_xor_sync(0xffffffffu, s2, m);
        }
        float mu  = s * (1.f / 128.f);
        float var = s2 * (1.f / 128.f) - mu * mu;
        float inv = rsqrtf(var + LN_EPS);
        if (grow < n) {
            float* orow = op + (size_t)grow * DD;
#pragma unroll
            for (int p = 0; p < 4; p++) {
                float2 o;
                o.x = fmaxf((v[2 * p]     - mu) * inv * gg[2 * p]     + be8[2 * p],     0.f);
                o.y = fmaxf((v[2 * p + 1] - mu) * inv * gg[2 * p + 1] + be8[2 * p + 1], 0.f);
                *reinterpret_cast<float2*>(orow + 2 * tx + 32 * p) = o;
            }
        }
    }
}

extern "C" void kernel_launch(void* const* d_in, const int* in_sizes, int n_in,
                              void* d_out, int out_size) {
    const float* features = (const float*)d_in[0];
    const int*   src      = (const int*)d_in[1];
    const int*   dst      = (const int*)d_in[2];
    const float* W1  = (const float*)d_in[3];
    const float* b1  = (const float*)d_in[4];
    const float* g1  = (const float*)d_in[5];
    const float* be1 = (const float*)d_in[6];
    const float* W2  = (const float*)d_in[7];
    const float* b2  = (const float*)d_in[8];
    const float* g2  = (const float*)d_in[9];
    const float* be2 = (const float*)d_in[10];
    float* out = (float*)d_out;

    int n = in_sizes[0] / DD;   // 50000
    int e = in_sizes[1];        // 800000

    int nBlocks    = (n + 255) / 256;
    int eBlocks    = (e + 255) / 256;
    int scanBlocks = (n + 1023) / 1024;
    int gathBlocks = (int)(((long long)n * 32 + 255) / 256);
    int gemmBlocks = (n + 63) / 64;

    // ---- CSR build (once, reused by both layers) ----
    zero_counts<<<nBlocks, 256>>>(n);
    deg_count<<<eBlocks, 256>>>(src, dst, e);
    scan_blocks<<<scanBlocks, 1024>>>(n);
    scan_partials<<<1, 64>>>(scanBlocks);
    finalize_off<<<nBlocks, 256>>>(n, e);
    fill_csr<<<eBlocks, 256>>>(src, dst, e);

    // ---- layer 1 ----
    gather_spmm<<<gathBlocks, 256>>>(features, n);
    gemm_ln_relu<<<gemmBlocks, 256>>>(W1, b1, g1, be1, nullptr, n);

    // ---- layer 2 ----
    gather_spmm<<<gathBlocks, 256>>>(nullptr, n);
    gemm_ln_relu<<<gemmBlocks, 256>>>(W2, b2, g2, be2, out, n);
}